// round 16
// baseline (speedup 1.0000x reference)
#include <cuda_runtime.h>

typedef unsigned long long u64;

#define BATCH   262144
#define DD      6
#define HH      100
#define TT      8
#define NPAIRS  (BATCH/2)
#define NTHREADS 256
#define NBLK    (NPAIRS/NTHREADS)   // 512 blocks, one pair per thread

// ---- packed f32x2 helpers (sm_103a) ----
__device__ __forceinline__ u64 F2FMA(u64 a, u64 b, u64 c) {
    u64 d; asm("fma.rn.f32x2 %0,%1,%2,%3;" : "=l"(d) : "l"(a), "l"(b), "l"(c)); return d;
}
__device__ __forceinline__ u64 F2MUL(u64 a, u64 b) {
    u64 d; asm("mul.rn.f32x2 %0,%1,%2;" : "=l"(d) : "l"(a), "l"(b)); return d;
}
__device__ __forceinline__ u64 F2ADD(u64 a, u64 b) {
    u64 d; asm("add.rn.f32x2 %0,%1,%2;" : "=l"(d) : "l"(a), "l"(b)); return d;
}
__device__ __forceinline__ u64 PACK2(float lo, float hi) {
    u64 d; asm("mov.b64 %0,{%1,%2};" : "=l"(d) : "f"(lo), "f"(hi)); return d;
}
__device__ __forceinline__ float2 UNPACK2(u64 v) {
    float2 r; asm("mov.b64 {%0,%1},%2;" : "=f"(r.x), "=f"(r.y) : "l"(v)); return r;
}
__device__ __forceinline__ u64 DUP(float s) { return PACK2(s, s); }

// hardware tanh (sm_75+): 1 MUFU op
__device__ __forceinline__ float TANHA(float x) {
    float r; asm("tanh.approx.f32 %0,%1;" : "=f"(r) : "f"(x)); return r;
}
__device__ __forceinline__ u64 TANH2(u64 a) {
    float2 x = UNPACK2(a);
    return PACK2(TANHA(x.x), TANHA(x.y));
}

// ---- MLP on 2 rows (one packed pair); layer-1 split into two 3-deep chains ----
// Same per-row op order as R15's A-chains -> bit-identical results.
// sW1 rows: 8 u64 per j = [w1*6 | b1 | pad]. sW2 rows: 6 u64 per j.
__device__ __forceinline__ void mlp2(const u64* __restrict__ sW1, const u64* __restrict__ sW2,
                                     const u64* __restrict__ sb2,
                                     const u64 yin[6], u64 out[6]) {
#pragma unroll
    for (int d = 0; d < DD; d++) out[d] = sb2[d];
#pragma unroll 1
    for (int j = 0; j < HH; j++) {
        const ulonglong2* r = (const ulonglong2*)(sW1 + j*8);
        ulonglong2 wa = r[0], wb = r[1], wc = r[2], wd = r[3];
        u64 s1 = F2FMA(wa.x, yin[0], wd.x);
        s1 = F2FMA(wa.y, yin[1], s1);
        s1 = F2FMA(wb.x, yin[2], s1);
        u64 s2 = F2MUL(wb.y, yin[3]);
        s2 = F2FMA(wc.x, yin[4], s2);
        s2 = F2FMA(wc.y, yin[5], s2);
        u64 t = TANH2(F2ADD(s1, s2));
        const ulonglong2* q = (const ulonglong2*)(sW2 + j*6);
        ulonglong2 va = q[0], vb = q[1], vc = q[2];
        out[0] = F2FMA(va.x, t, out[0]);
        out[1] = F2FMA(va.y, t, out[1]);
        out[2] = F2FMA(vb.x, t, out[2]);
        out[3] = F2FMA(vb.y, t, out[3]);
        out[4] = F2FMA(vc.x, t, out[4]);
        out[5] = F2FMA(vc.y, t, out[5]);
    }
}

__device__ __forceinline__ void axpy6(u64 t[6], const u64 k[6], u64 cc) {
#pragma unroll
    for (int d = 0; d < DD; d++) t[d] = F2FMA(cc, k[d], t[d]);
}
__device__ __forceinline__ void setax6(u64 t[6], const u64 y[6], const u64 k[6], u64 cc) {
#pragma unroll
    for (int d = 0; d < DD; d++) t[d] = F2FMA(cc, k[d], y[d]);
}

__global__ void __launch_bounds__(NTHREADS, 2)
ode_kernel(const float* __restrict__ in_seq, const float* __restrict__ W1,
           const float* __restrict__ b1, const float* __restrict__ W2,
           const float* __restrict__ b2, const float* __restrict__ Wl,
           const float* __restrict__ bl, float* __restrict__ out) {
    const float A21f = 0.2f;
    const float A31f = 3.f/40.f,  A32f = 9.f/40.f;
    const float A41f = 44.f/45.f, A42f = -56.f/15.f, A43f = 32.f/9.f;
    const float A51f = 19372.f/6561.f, A52f = -25360.f/2187.f, A53f = 64448.f/6561.f, A54f = -212.f/729.f;
    const float A61f = 9017.f/3168.f,  A62f = -355.f/33.f,     A63f = 46732.f/5247.f,
                A64f = 49.f/176.f,     A65f = -5103.f/18656.f;
    const float B1f = 35.f/384.f, B3f = 500.f/1113.f, B4f = 125.f/192.f, B5f = -2187.f/6784.f, B6f = 11.f/84.f;

    __shared__ __align__(16) u64 sW1[HH*8];
    __shared__ __align__(16) u64 sW2[HH*6];
    __shared__ __align__(16) u64 sb2[DD];

    const int tid = threadIdx.x;

    for (int i = tid; i < HH; i += NTHREADS) {
#pragma unroll
        for (int d = 0; d < DD; d++) {
            float w1v = W1[i*DD + d];   sW1[i*8 + d] = PACK2(w1v, w1v);
            float w2v = W2[d*HH + i];   sW2[i*6 + d] = PACK2(w2v, w2v);
        }
        float bv = b1[i];
        sW1[i*8 + 6] = PACK2(bv, bv);
        sW1[i*8 + 7] = 0ull;
    }
    if (tid < DD) { float v = b2[tid]; sb2[tid] = PACK2(v, v); }
    __syncthreads();

    // single fixed h = 1 dopri5 step
    const u64 c21 = DUP(A21f);
    const u64 c31 = DUP(A31f), c32 = DUP(A32f);
    const u64 c41 = DUP(A41f), c42 = DUP(A42f), c43 = DUP(A43f);
    const u64 c51 = DUP(A51f), c52 = DUP(A52f), c53 = DUP(A53f), c54 = DUP(A54f);
    const u64 c61 = DUP(A61f), c62 = DUP(A62f), c63 = DUP(A63f), c64 = DUP(A64f), c65 = DUP(A65f);
    const u64 cb1 = DUP(B1f), cb3 = DUP(B3f), cb4 = DUP(B4f), cb5 = DUP(B5f), cb6 = DUP(B6f);

    // exactly one pair per thread
    const int p = blockIdx.x * NTHREADS + tid;

    u64 y[6], k1[6], k2[6], k3[6], k4[6], k5[6], tmp[6], yp[6];
    {
        const float* r0 = in_seq + (size_t)(2*p) * (TT*DD) + (TT-1)*DD;
        const float* r1 = r0 + TT*DD;
#pragma unroll
        for (int d = 0; d < DD; d++) y[d] = PACK2(r0[d], r1[d]);
    }
    // k1 = f(y)
    mlp2(sW1, sW2, sb2, y, k1);
    // stage 2
    setax6(tmp, y, k1, c21);
    mlp2(sW1, sW2, sb2, tmp, k2);
    // stage 3
    setax6(tmp, y, k1, c31); axpy6(tmp, k2, c32);
    mlp2(sW1, sW2, sb2, tmp, k3);
    // stage 4
    setax6(tmp, y, k1, c41); axpy6(tmp, k2, c42); axpy6(tmp, k3, c43);
    mlp2(sW1, sW2, sb2, tmp, k4);
    // stage 5
    setax6(tmp, y, k1, c51); axpy6(tmp, k2, c52); axpy6(tmp, k3, c53); axpy6(tmp, k4, c54);
    mlp2(sW1, sW2, sb2, tmp, k5);
    // stage-6 input (k2 dies here)
    setax6(tmp, y, k1, c61); axpy6(tmp, k2, c62); axpy6(tmp, k3, c63);
    axpy6(tmp, k4, c64); axpy6(tmp, k5, c65);
    // partial y_new BEFORE stage-6 MLP (k1,k3,k4,k5 die here)
    setax6(yp, y, k1, cb1); axpy6(yp, k3, cb3); axpy6(yp, k4, cb4); axpy6(yp, k5, cb5);
    // stage 6
    mlp2(sW1, sW2, sb2, tmp, k2);               // k2 = k6
    axpy6(yp, k2, cb6);                          // y_new complete

    // output: out[b] = dot(y_new[b], Wl) + bl
    float wl[DD];
#pragma unroll
    for (int d = 0; d < DD; d++) wl[d] = Wl[d];
    float o0 = bl[0], o1 = o0;
#pragma unroll
    for (int d = 0; d < DD; d++) {
        float2 yv = UNPACK2(yp[d]);
        o0 = fmaf(yv.x, wl[d], o0);
        o1 = fmaf(yv.y, wl[d], o1);
    }
    out[2*p]   = o0;
    out[2*p+1] = o1;
}

extern "C" void kernel_launch(void* const* d_in, const int* in_sizes, int n_in,
                              void* d_out, int out_size) {
    const float* in_seq = (const float*)d_in[0];
    const float* W1 = (const float*)d_in[1];
    const float* b1 = (const float*)d_in[2];
    const float* W2 = (const float*)d_in[3];
    const float* b2 = (const float*)d_in[4];
    const float* Wl = (const float*)d_in[5];
    const float* bl = (const float*)d_in[6];
    float* out = (float*)d_out;
    ode_kernel<<<NBLK, NTHREADS>>>(in_seq, W1, b1, W2, b2, Wl, bl, out);
}